// round 9
// baseline (speedup 1.0000x reference)
#include <cuda_runtime.h>
#include <cstdint>
#include <cstddef>

// ---------------- problem constants ----------------
constexpr int N_  = 16;
constexpr int D_  = 16;
constexpr int S_  = 112;
constexpr int SS_ = S_ * S_;          // 12544
constexpr int M_  = 2;
constexpr int V_  = 7829;
constexpr int K_  = 512;
constexpr int NM_ = N_ * M_;          // 32
constexpr int NCH = 8;                // v-chunks
constexpr int VCH = (V_ + NCH - 1) / NCH;   // 979
constexpr int CAP = 64;               // candidate slots per (k, chunk)
constexpr int CYB = 16;               // k_cyc grid.y
constexpr float TSCALE = 20.0f;       // 1/T
constexpr float THRESH = -20.0f;      // keep 20*sim + tk > -20  (A > ~2e-9)

// ---------------- static device scratch ----------------
__device__ float g_sim[(size_t)NM_ * V_ * K_];    // [nm][v][k]
__device__ float g_sampled[N_ * K_ * D_];
__device__ float g_fx[N_ * K_], g_fy[N_ * K_];
__device__ float g_rpmax[NM_ * NCH * K_];
__device__ float g_rpsum[NM_ * NCH * K_];
__device__ float g_tk[NM_ * K_];                  // -20*rmax[k]
__device__ float g_rk[NM_ * K_];                  // 1/rsum[k]
__device__ float g_av[NM_ * V_];                  // -20*cmax[v] - ln(csum[v])
__device__ int   g_cnt[NM_ * NCH * K_];
__device__ uint2 g_cand[(size_t)NM_ * NCH * K_ * CAP];   // {v, e=exp(20sim+tk)}
__device__ float g_partial[NM_ * CYB];
__device__ int   g_is64;

// ---------------- fast exp: pure FMA, branchless, ~1.3e-6 rel err ----------------
static __device__ __forceinline__ float fexp(float x) {
    float y = x * 1.4426950408889634f;           // x/ln2
    y = fminf(y, 126.0f);
    y = fmaxf(y, -127.0f);                        // underflow -> denormal/0
    float fl = floorf(y);
    float f  = y - fl;                            // [0,1)
    float p = 1.5252733804e-5f;
    p = fmaf(p, f, 1.5403530393e-4f);
    p = fmaf(p, f, 1.3333558146e-3f);
    p = fmaf(p, f, 9.6181291076e-3f);
    p = fmaf(p, f, 5.5504108664e-2f);
    p = fmaf(p, f, 2.4022650696e-1f);
    p = fmaf(p, f, 6.9314718056e-1f);
    p = fmaf(p, f, 1.0f);
    return __int_as_float(__float_as_int(p) + (((int)fl) << 23));
}

static __device__ __forceinline__ float max4(float4 a) {
    return fmaxf(fmaxf(a.x, a.y), fmaxf(a.z, a.w));
}

// ---------------- K0: detect int64 vs int32 indices ----------------
__global__ void k_detect(const int* __restrict__ w) {
    __shared__ int s_allzero;
    if (threadIdx.x == 0) s_allzero = 1;
    __syncthreads();
    int nz = 0;
    for (int i = threadIdx.x * 2 + 1; i < N_ * K_; i += blockDim.x * 2)
        if (w[i] != 0) nz = 1;
    if (nz) atomicAnd(&s_allzero, 0);
    __syncthreads();
    if (threadIdx.x == 0) g_is64 = s_allzero;
}

// ---------------- K1: gather + normalize sampled embeddings ----------------
__global__ void k_sample(const float* __restrict__ pix, const void* __restrict__ idxraw) {
    int t = blockIdx.x * blockDim.x + threadIdx.x;
    if (t >= N_ * K_) return;
    long long idx;
    if (g_is64) idx = ((const long long*)idxraw)[t];
    else        idx = (long long)((const int*)idxraw)[t];
    int n = t / K_;
    int p = (int)idx;
    g_fx[t] = (float)(p / S_);
    g_fy[t] = (float)(p % S_);
    const float* base = pix + (size_t)n * D_ * SS_ + p;
    float v[16]; float ss = 0.f;
#pragma unroll
    for (int d = 0; d < 16; d++) { v[d] = base[(size_t)d * SS_]; ss = fmaf(v[d], v[d], ss); }
    float inv = 1.0f / fmaxf(sqrtf(ss), 1e-6f);
#pragma unroll
    for (int d = 0; d < 16; d++) g_sampled[t * 16 + d] = v[d] * inv;
}

// ---------------- K2: sim[nm][v][k] + per-chunk row max (over v) ----------------
__global__ void __launch_bounds__(512) k_sim(const float* __restrict__ mesh) {
    int nm = blockIdx.x, ch = blockIdx.y;
    int k  = threadIdx.x;
    int n = nm / M_, m = nm % M_;
    float sk[16];
    const float* sp = &g_sampled[(n * K_ + k) * 16];
#pragma unroll
    for (int d = 0; d < 16; d++) sk[d] = sp[d];
    int v0 = ch * VCH;
    int v1 = min(v0 + VCH, V_);
    float mx = -1e30f;
    float* simbase = g_sim + (size_t)nm * V_ * K_;
    const float4* mb = (const float4*)(mesh + (size_t)m * V_ * D_);
    for (int v = v0; v < v1; v++) {
        float4 m0 = mb[v * 4 + 0], m1 = mb[v * 4 + 1];
        float4 m2 = mb[v * 4 + 2], m3 = mb[v * 4 + 3];
        float s;
        s =          sk[0]  * m0.x;     s = fmaf(sk[1],  m0.y, s);
        s = fmaf(sk[2],  m0.z, s);      s = fmaf(sk[3],  m0.w, s);
        s = fmaf(sk[4],  m1.x, s);      s = fmaf(sk[5],  m1.y, s);
        s = fmaf(sk[6],  m1.z, s);      s = fmaf(sk[7],  m1.w, s);
        s = fmaf(sk[8],  m2.x, s);      s = fmaf(sk[9],  m2.y, s);
        s = fmaf(sk[10], m2.z, s);      s = fmaf(sk[11], m2.w, s);
        s = fmaf(sk[12], m3.x, s);      s = fmaf(sk[13], m3.y, s);
        s = fmaf(sk[14], m3.z, s);      s = fmaf(sk[15], m3.w, s);
        simbase[(size_t)v * K_ + k] = s;
        mx = fmaxf(mx, s);
    }
    g_rpmax[(nm * NCH + ch) * K_ + k] = mx;
}

// ---------------- K2b: combine chunk maxes -> tk ----------------
__global__ void k_rowmax() {
    int t = blockIdx.x * blockDim.x + threadIdx.x;
    if (t >= NM_ * K_) return;
    int nm = t / K_, k = t % K_;
    float mx = -1e30f;
#pragma unroll
    for (int c = 0; c < NCH; c++) mx = fmaxf(mx, g_rpmax[(nm * NCH + c) * K_ + k]);
    g_tk[t] = -TSCALE * mx;
}

// ---------------- K3: scan -> candidate lists + row sums ----------------
// Thread (nm, ch, k) scans its v-range in order; keeps v with 20*sim+tk > -20.
// Deterministic (per-thread sequential order).
__global__ void __launch_bounds__(512) k_scan() {
    int nm = blockIdx.x, ch = blockIdx.y;
    int k  = threadIdx.x;
    float tk = g_tk[nm * K_ + k];
    int v0 = ch * VCH, v1 = min(v0 + VCH, V_);
    const float* sb = g_sim + (size_t)nm * V_ * K_;
    uint2* cl = g_cand + ((size_t)((nm * NCH + ch) * K_ + k)) * CAP;
    int cnt = 0; float rs = 0.f;
    for (int v = v0; v < v1; v++) {
        float t = fmaf(TSCALE, sb[(size_t)v * K_ + k], tk);
        if (t > THRESH) {
            float e = fexp(t);
            rs += e;
            if (cnt < CAP) cl[cnt] = make_uint2((unsigned)v, __float_as_uint(e));
            cnt++;
        }
    }
    g_cnt[(nm * NCH + ch) * K_ + k] = min(cnt, CAP);
    g_rpsum[(nm * NCH + ch) * K_ + k] = rs;
}

// ---------------- K3b: finalize rows -> rk ----------------
__global__ void k_rowfin() {
    int t = blockIdx.x * blockDim.x + threadIdx.x;
    if (t >= NM_ * K_) return;
    int nm = t / K_, k = t % K_;
    float s = 0.f;
#pragma unroll
    for (int c = 0; c < NCH; c++) s += g_rpsum[(nm * NCH + c) * K_ + k];
    g_rk[t] = 1.0f / s;
}

// ---------------- K4: column stats -> a_v = -20*cmax - ln(csum) ----------------
__global__ void __launch_bounds__(256) k_colstats() {
    int nm = blockIdx.x;
    int v  = blockIdx.y * 8 + (threadIdx.x >> 5);
    int lane = threadIdx.x & 31;
    if (v >= V_) return;
    const float4* row = (const float4*)(g_sim + ((size_t)nm * V_ + v) * K_);
    float4 a = row[lane], b = row[lane + 32], c = row[lane + 64], d = row[lane + 96];
    float mx = fmaxf(fmaxf(max4(a), max4(b)), fmaxf(max4(c), max4(d)));
#pragma unroll
    for (int o = 16; o > 0; o >>= 1) mx = fmaxf(mx, __shfl_xor_sync(0xffffffffu, mx, o));
    float th = mx - 1.0f;          // contributions below exp(-20): negligible
    float s = 0.f;
    #define CADD(x) { float _x = (x); if (_x > th) s += fexp(TSCALE * (_x - mx)); }
    CADD(a.x) CADD(a.y) CADD(a.z) CADD(a.w)
    CADD(b.x) CADD(b.y) CADD(b.z) CADD(b.w)
    CADD(c.x) CADD(c.y) CADD(c.z) CADD(c.w)
    CADD(d.x) CADD(d.y) CADD(d.z) CADD(d.w)
    #undef CADD
#pragma unroll
    for (int o = 16; o > 0; o >>= 1) s += __shfl_xor_sync(0xffffffffu, s, o);
    if (lane == 0)
        g_av[(size_t)nm * V_ + v] = fmaf(-TSCALE, mx, -logf(s));
}

// ---------------- K5: sparse cycle + fused loss ----------------
// Warp handles 4 k's; for each candidate v of row k:
//   C[k, q] += (e/rsum_k) * exp(20*sim[v][q] + a_v)   for all 512 q (16 per lane)
// then epilogue part += (dist2[k,q] * C)^2.
__global__ void __launch_bounds__(256) k_cyc() {
    __shared__ float sfx[K_], sfy[K_];
    __shared__ float red[256];
    int nm = blockIdx.x, by = blockIdx.y;
    int n = nm / M_;
    int tid = threadIdx.x, w = tid >> 5, lane = tid & 31;
    for (int i = tid; i < K_; i += 256) {
        sfx[i] = g_fx[n * K_ + i];
        sfy[i] = g_fy[n * K_ + i];
    }
    __syncthreads();

    float part = 0.f;
#pragma unroll 1
    for (int i = 0; i < 4; i++) {
        int k = by * 32 + w * 4 + i;
        float rkk = g_rk[nm * K_ + k];
        float acc[16];
#pragma unroll
        for (int j = 0; j < 16; j++) acc[j] = 0.f;

        for (int ch = 0; ch < NCH; ch++) {
            int base = (nm * NCH + ch) * K_ + k;
            int cnt = g_cnt[base];
            const uint2* cl = g_cand + (size_t)base * CAP;
            for (int c = 0; c < cnt; c++) {
                uint2 ce = cl[c];                        // broadcast load
                float wv = __uint_as_float(ce.y) * rkk;  // A[k,v]
                float av = g_av[(size_t)nm * V_ + ce.x];
                const float* row = g_sim + ((size_t)nm * V_ + ce.x) * K_;
                float rv[16];
#pragma unroll
                for (int j = 0; j < 16; j++) rv[j] = __ldg(&row[j * 32 + lane]);
#pragma unroll
                for (int j = 0; j < 16; j++)
                    acc[j] = fmaf(wv, fexp(fmaf(TSCALE, rv[j], av)), acc[j]);
            }
        }

        float xk = sfx[k], yk = sfy[k];
#pragma unroll
        for (int j = 0; j < 16; j++) {
            int q = j * 32 + lane;
            float dx = xk - sfx[q];
            float dy = yk - sfy[q];
            float dist = fmaf(dx, dx, dy * dy);          // squared distance
            float wt = dist * acc[j];                    // d^2 * C
            part = fmaf(wt, wt, part);
        }
    }
    red[tid] = part;
    __syncthreads();
    for (int o = 128; o > 0; o >>= 1) {
        if (tid < o) red[tid] += red[tid + o];
        __syncthreads();
    }
    if (tid == 0) g_partial[nm * CYB + by] = red[0];
}

// ---------------- K6: final sqrt + mean ----------------
__global__ void k_final(float* __restrict__ out) {
    int t = threadIdx.x;           // 32 threads, one per nm
    float s = 0.f;
#pragma unroll
    for (int pr = 0; pr < CYB; pr++) s += g_partial[t * CYB + pr];
    float l = sqrtf(s);
#pragma unroll
    for (int o = 16; o > 0; o >>= 1) l += __shfl_xor_sync(0xffffffffu, l, o);
    if (t == 0) out[0] = l / (float)NM_;
}

// ---------------- launch ----------------
extern "C" void kernel_launch(void* const* d_in, const int* in_sizes, int n_in,
                              void* d_out, int out_size) {
    const float* pix  = (const float*)d_in[0];
    const float* mesh = (const float*)d_in[1];
    const void*  idx  = d_in[2];
    float* out = (float*)d_out;
    (void)in_sizes; (void)n_in; (void)out_size;

    k_detect<<<1, 256>>>((const int*)idx);
    k_sample<<<(N_ * K_ + 255) / 256, 256>>>(pix, idx);
    k_sim<<<dim3(NM_, NCH), 512>>>(mesh);
    k_rowmax<<<(NM_ * K_ + 255) / 256, 256>>>();
    k_scan<<<dim3(NM_, NCH), 512>>>();
    k_rowfin<<<(NM_ * K_ + 255) / 256, 256>>>();
    k_colstats<<<dim3(NM_, (V_ + 7) / 8), 256>>>();
    k_cyc<<<dim3(NM_, CYB), 256>>>();
    k_final<<<1, 32>>>(out);
}

// round 11
// speedup vs baseline: 1.3371x; 1.3371x over previous
#include <cuda_runtime.h>
#include <cuda_bf16.h>
#include <cstdint>
#include <cstddef>

// ---------------- problem constants ----------------
constexpr int N_  = 16;
constexpr int D_  = 16;
constexpr int S_  = 112;
constexpr int SS_ = S_ * S_;          // 12544
constexpr int M_  = 2;
constexpr int V_  = 7829;
constexpr int K_  = 512;
constexpr int KW_ = K_ / 2;           // 256 bf16x2 words per row
constexpr int NM_ = N_ * M_;          // 32
constexpr int NCH = 8;                // v-chunks
constexpr int VCH = (V_ + NCH - 1) / NCH;   // 979
constexpr int CAP = 48;               // candidate slots per (k, chunk)
constexpr int CYB = 16;               // k_cyc grid.y
constexpr float TSCALE = 20.0f;       // 1/T
constexpr float THRESH = -13.0f;      // keep 20*sim - 20*rmax > -13 (dropped mass ~1e-6)

// ---------------- static device scratch ----------------
__device__ float    g_sim[(size_t)NM_ * V_ * K_];   // [nm][v][k]
__device__ uint32_t g_bt[(size_t)NM_ * V_ * KW_];   // [nm][v][k/2] bf16x2 B-tilde rows
__device__ float g_sampled[N_ * K_ * D_];
__device__ float g_fx[N_ * K_], g_fy[N_ * K_];
__device__ float g_rpmax[NM_ * NCH * K_];
__device__ float g_rpsum[NM_ * NCH * K_];
__device__ float g_tk[NM_ * K_];                  // -20*rmax[k]
__device__ float g_rk[NM_ * K_];                  // 1/rsum[k]
__device__ int   g_cnt[NM_ * NCH * K_];
__device__ uint2 g_cand[(size_t)NM_ * NCH * K_ * CAP];   // {v, e=exp(20sim+tk)}
__device__ float g_partial[NM_ * CYB];
__device__ int   g_is64;

// ---------------- fast exp: pure FMA, branchless, ~1.3e-6 rel err ----------------
static __device__ __forceinline__ float fexp(float x) {
    float y = x * 1.4426950408889634f;           // x/ln2
    y = fminf(y, 126.0f);
    y = fmaxf(y, -127.0f);                        // underflow -> denormal/0
    float fl = floorf(y);
    float f  = y - fl;                            // [0,1)
    float p = 1.5252733804e-5f;
    p = fmaf(p, f, 1.5403530393e-4f);
    p = fmaf(p, f, 1.3333558146e-3f);
    p = fmaf(p, f, 9.6181291076e-3f);
    p = fmaf(p, f, 5.5504108664e-2f);
    p = fmaf(p, f, 2.4022650696e-1f);
    p = fmaf(p, f, 6.9314718056e-1f);
    p = fmaf(p, f, 1.0f);
    return __int_as_float(__float_as_int(p) + (((int)fl) << 23));
}

static __device__ __forceinline__ float max4(float4 a) {
    return fmaxf(fmaxf(a.x, a.y), fmaxf(a.z, a.w));
}

static __device__ __forceinline__ uint32_t bf16pair(float lo, float hi) {
    __nv_bfloat162 p = __floats2bfloat162_rn(lo, hi);   // .x = lo (low 16 bits)
    return *reinterpret_cast<uint32_t*>(&p);
}

// ---------------- K0: detect int64 vs int32 indices ----------------
__global__ void k_detect(const int* __restrict__ w) {
    __shared__ int s_allzero;
    if (threadIdx.x == 0) s_allzero = 1;
    __syncthreads();
    int nz = 0;
    for (int i = threadIdx.x * 2 + 1; i < N_ * K_; i += blockDim.x * 2)
        if (w[i] != 0) nz = 1;
    if (nz) atomicAnd(&s_allzero, 0);
    __syncthreads();
    if (threadIdx.x == 0) g_is64 = s_allzero;
}

// ---------------- K1: gather + normalize sampled embeddings ----------------
__global__ void k_sample(const float* __restrict__ pix, const void* __restrict__ idxraw) {
    int t = blockIdx.x * blockDim.x + threadIdx.x;
    if (t >= N_ * K_) return;
    long long idx;
    if (g_is64) idx = ((const long long*)idxraw)[t];
    else        idx = (long long)((const int*)idxraw)[t];
    int n = t / K_;
    int p = (int)idx;
    g_fx[t] = (float)(p / S_);
    g_fy[t] = (float)(p % S_);
    const float* base = pix + (size_t)n * D_ * SS_ + p;
    float v[16]; float ss = 0.f;
#pragma unroll
    for (int d = 0; d < 16; d++) { v[d] = base[(size_t)d * SS_]; ss = fmaf(v[d], v[d], ss); }
    float inv = 1.0f / fmaxf(sqrtf(ss), 1e-6f);
#pragma unroll
    for (int d = 0; d < 16; d++) g_sampled[t * 16 + d] = v[d] * inv;
}

// ---------------- K2: sim[nm][v][k] + per-chunk row max (over v) ----------------
__global__ void __launch_bounds__(512) k_sim(const float* __restrict__ mesh) {
    int nm = blockIdx.x, ch = blockIdx.y;
    int k  = threadIdx.x;
    int n = nm / M_, m = nm % M_;
    float sk[16];
    const float* sp = &g_sampled[(n * K_ + k) * 16];
#pragma unroll
    for (int d = 0; d < 16; d++) sk[d] = sp[d];
    int v0 = ch * VCH;
    int v1 = min(v0 + VCH, V_);
    float mx = -1e30f;
    float* simbase = g_sim + (size_t)nm * V_ * K_;
    const float4* mb = (const float4*)(mesh + (size_t)m * V_ * D_);
    for (int v = v0; v < v1; v++) {
        float4 m0 = mb[v * 4 + 0], m1 = mb[v * 4 + 1];
        float4 m2 = mb[v * 4 + 2], m3 = mb[v * 4 + 3];
        float s;
        s =          sk[0]  * m0.x;     s = fmaf(sk[1],  m0.y, s);
        s = fmaf(sk[2],  m0.z, s);      s = fmaf(sk[3],  m0.w, s);
        s = fmaf(sk[4],  m1.x, s);      s = fmaf(sk[5],  m1.y, s);
        s = fmaf(sk[6],  m1.z, s);      s = fmaf(sk[7],  m1.w, s);
        s = fmaf(sk[8],  m2.x, s);      s = fmaf(sk[9],  m2.y, s);
        s = fmaf(sk[10], m2.z, s);      s = fmaf(sk[11], m2.w, s);
        s = fmaf(sk[12], m3.x, s);      s = fmaf(sk[13], m3.y, s);
        s = fmaf(sk[14], m3.z, s);      s = fmaf(sk[15], m3.w, s);
        simbase[(size_t)v * K_ + k] = s;
        mx = fmaxf(mx, s);
    }
    g_rpmax[(nm * NCH + ch) * K_ + k] = mx;
}

// ---------------- K2b: combine chunk maxes -> tk ----------------
__global__ void k_rowmax() {
    int t = blockIdx.x * blockDim.x + threadIdx.x;
    if (t >= NM_ * K_) return;
    int nm = t / K_, k = t % K_;
    float mx = -1e30f;
#pragma unroll
    for (int c = 0; c < NCH; c++) mx = fmaxf(mx, g_rpmax[(nm * NCH + c) * K_ + k]);
    g_tk[t] = -TSCALE * mx;
}

// ---------------- K3: scan -> candidate lists + row sums ----------------
// Thread (nm, ch, k) scans its v-range in order; keeps v with 20*sim+tk > THRESH.
// Deterministic (per-thread sequential order).
__global__ void __launch_bounds__(512) k_scan() {
    int nm = blockIdx.x, ch = blockIdx.y;
    int k  = threadIdx.x;
    float tk = g_tk[nm * K_ + k];
    int v0 = ch * VCH, v1 = min(v0 + VCH, V_);
    const float* sb = g_sim + (size_t)nm * V_ * K_;
    uint2* cl = g_cand + ((size_t)((nm * NCH + ch) * K_ + k)) * CAP;
    int cnt = 0; float rs = 0.f;
    for (int v = v0; v < v1; v++) {
        float t = fmaf(TSCALE, sb[(size_t)v * K_ + k], tk);
        if (t > THRESH) {
            float e = fexp(t);
            rs += e;
            if (cnt < CAP) cl[cnt] = make_uint2((unsigned)v, __float_as_uint(e));
            cnt++;
        }
    }
    g_cnt[(nm * NCH + ch) * K_ + k] = min(cnt, CAP);
    g_rpsum[(nm * NCH + ch) * K_ + k] = rs;
}

// ---------------- K3b: finalize rows -> rk ----------------
__global__ void k_rowfin() {
    int t = blockIdx.x * blockDim.x + threadIdx.x;
    if (t >= NM_ * K_) return;
    int nm = t / K_, k = t % K_;
    float s = 0.f;
#pragma unroll
    for (int c = 0; c < NCH; c++) s += g_rpsum[(nm * NCH + c) * K_ + k];
    g_rk[t] = 1.0f / s;
}

// ---------------- K4: column stats + B-tilde rows (bf16) ----------------
// Warp per (nm, v): cmax/csum over k, then write B[v][q] = exp(20(s-cmax))/csum
// as packed bf16x2 (word w holds q=2w, 2w+1).
__global__ void __launch_bounds__(256) k_colbt() {
    int nm = blockIdx.x;
    int v  = blockIdx.y * 8 + (threadIdx.x >> 5);
    int lane = threadIdx.x & 31;
    if (v >= V_) return;
    const float4* row = (const float4*)(g_sim + ((size_t)nm * V_ + v) * K_);
    float4 a = row[lane], b = row[lane + 32], c = row[lane + 64], d = row[lane + 96];
    float mx = fmaxf(fmaxf(max4(a), max4(b)), fmaxf(max4(c), max4(d)));
#pragma unroll
    for (int o = 16; o > 0; o >>= 1) mx = fmaxf(mx, __shfl_xor_sync(0xffffffffu, mx, o));
    float nmx = -TSCALE * mx;
    float ea0 = fexp(fmaf(TSCALE, a.x, nmx)), ea1 = fexp(fmaf(TSCALE, a.y, nmx));
    float ea2 = fexp(fmaf(TSCALE, a.z, nmx)), ea3 = fexp(fmaf(TSCALE, a.w, nmx));
    float eb0 = fexp(fmaf(TSCALE, b.x, nmx)), eb1 = fexp(fmaf(TSCALE, b.y, nmx));
    float eb2 = fexp(fmaf(TSCALE, b.z, nmx)), eb3 = fexp(fmaf(TSCALE, b.w, nmx));
    float ec0 = fexp(fmaf(TSCALE, c.x, nmx)), ec1 = fexp(fmaf(TSCALE, c.y, nmx));
    float ec2 = fexp(fmaf(TSCALE, c.z, nmx)), ec3 = fexp(fmaf(TSCALE, c.w, nmx));
    float ed0 = fexp(fmaf(TSCALE, d.x, nmx)), ed1 = fexp(fmaf(TSCALE, d.y, nmx));
    float ed2 = fexp(fmaf(TSCALE, d.z, nmx)), ed3 = fexp(fmaf(TSCALE, d.w, nmx));
    float s = ((ea0 + ea1) + (ea2 + ea3)) + ((eb0 + eb1) + (eb2 + eb3))
            + ((ec0 + ec1) + (ec2 + ec3)) + ((ed0 + ed1) + (ed2 + ed3));
#pragma unroll
    for (int o = 16; o > 0; o >>= 1) s += __shfl_xor_sync(0xffffffffu, s, o);
    float inv = 1.0f / s;

    uint32_t* bout = g_bt + ((size_t)nm * V_ + v) * KW_;
    uint2 w;
    // segment a: q = 4*lane .. 4*lane+3  -> words 2*lane, 2*lane+1
    w.x = bf16pair(ea0 * inv, ea1 * inv);
    w.y = bf16pair(ea2 * inv, ea3 * inv);
    *(uint2*)&bout[2 * lane] = w;
    w.x = bf16pair(eb0 * inv, eb1 * inv);
    w.y = bf16pair(eb2 * inv, eb3 * inv);
    *(uint2*)&bout[2 * lane + 64] = w;
    w.x = bf16pair(ec0 * inv, ec1 * inv);
    w.y = bf16pair(ec2 * inv, ec3 * inv);
    *(uint2*)&bout[2 * lane + 128] = w;
    w.x = bf16pair(ed0 * inv, ed1 * inv);
    w.y = bf16pair(ed2 * inv, ed3 * inv);
    *(uint2*)&bout[2 * lane + 192] = w;
}

// ---------------- K5: sparse cycle (pure FMA) + fused loss ----------------
// Warp handles 4 k's; for each candidate v of row k:
//   C[k, q] += A[k,v] * B[v, q]   for all 512 q (16 per lane, from 8 bf16x2 words)
// then part += (dist2[k,q] * C)^2.
__global__ void __launch_bounds__(256) k_cyc() {
    __shared__ float sfx[K_], sfy[K_];
    __shared__ float red[256];
    int nm = blockIdx.x, by = blockIdx.y;
    int n = nm / M_;
    int tid = threadIdx.x, w = tid >> 5, lane = tid & 31;
    for (int i = tid; i < K_; i += 256) {
        sfx[i] = g_fx[n * K_ + i];
        sfy[i] = g_fy[n * K_ + i];
    }
    __syncthreads();

    float part = 0.f;
#pragma unroll 1
    for (int i = 0; i < 4; i++) {
        int k = by * 32 + w * 4 + i;
        float rkk = g_rk[nm * K_ + k];
        float acc[16];
#pragma unroll
        for (int j = 0; j < 16; j++) acc[j] = 0.f;

        for (int ch = 0; ch < NCH; ch++) {
            int base = (nm * NCH + ch) * K_ + k;
            int cnt = g_cnt[base];
            const uint2* cl = g_cand + (size_t)base * CAP;
            for (int c = 0; c < cnt; c++) {
                uint2 ce = cl[c];                        // broadcast load
                float wv = __uint_as_float(ce.y) * rkk;  // A[k,v]
                const uint32_t* row = g_bt + ((size_t)nm * V_ + ce.x) * KW_;
                uint32_t rw[8];
#pragma unroll
                for (int j = 0; j < 8; j++) rw[j] = __ldg(&row[j * 32 + lane]);
#pragma unroll
                for (int j = 0; j < 8; j++) {
                    float2 f = __bfloat1622float2(*reinterpret_cast<__nv_bfloat162*>(&rw[j]));
                    acc[2 * j]     = fmaf(wv, f.x, acc[2 * j]);
                    acc[2 * j + 1] = fmaf(wv, f.y, acc[2 * j + 1]);
                }
            }
        }

        float xk = sfx[k], yk = sfy[k];
#pragma unroll
        for (int j = 0; j < 8; j++) {
            int q0 = 2 * (j * 32 + lane);
            float dx0 = xk - sfx[q0], dy0 = yk - sfy[q0];
            float dist0 = fmaf(dx0, dx0, dy0 * dy0);
            float wt0 = dist0 * acc[2 * j];
            part = fmaf(wt0, wt0, part);
            float dx1 = xk - sfx[q0 + 1], dy1 = yk - sfy[q0 + 1];
            float dist1 = fmaf(dx1, dx1, dy1 * dy1);
            float wt1 = dist1 * acc[2 * j + 1];
            part = fmaf(wt1, wt1, part);
        }
    }
    red[tid] = part;
    __syncthreads();
    for (int o = 128; o > 0; o >>= 1) {
        if (tid < o) red[tid] += red[tid + o];
        __syncthreads();
    }
    if (tid == 0) g_partial[nm * CYB + by] = red[0];
}

// ---------------- K6: final sqrt + mean ----------------
__global__ void k_final(float* __restrict__ out) {
    int t = threadIdx.x;           // 32 threads, one per nm
    float s = 0.f;
#pragma unroll
    for (int pr = 0; pr < CYB; pr++) s += g_partial[t * CYB + pr];
    float l = sqrtf(s);
#pragma unroll
    for (int o = 16; o > 0; o >>= 1) l += __shfl_xor_sync(0xffffffffu, l, o);
    if (t == 0) out[0] = l / (float)NM_;
}

// ---------------- launch ----------------
extern "C" void kernel_launch(void* const* d_in, const int* in_sizes, int n_in,
                              void* d_out, int out_size) {
    const float* pix  = (const float*)d_in[0];
    const float* mesh = (const float*)d_in[1];
    const void*  idx  = d_in[2];
    float* out = (float*)d_out;
    (void)in_sizes; (void)n_in; (void)out_size;

    k_detect<<<1, 256>>>((const int*)idx);
    k_sample<<<(N_ * K_ + 255) / 256, 256>>>(pix, idx);
    k_sim<<<dim3(NM_, NCH), 512>>>(mesh);
    k_rowmax<<<(NM_ * K_ + 255) / 256, 256>>>();
    k_scan<<<dim3(NM_, NCH), 512>>>();
    k_rowfin<<<(NM_ * K_ + 255) / 256, 256>>>();
    k_colbt<<<dim3(NM_, (V_ + 7) / 8), 256>>>();
    k_cyc<<<dim3(NM_, CYB), 256>>>();
    k_final<<<1, 32>>>(out);
}